// round 2
// baseline (speedup 1.0000x reference)
#include <cuda_runtime.h>

// Shapes fixed by the problem: B=8, C=512, H=W=64 -> N=4096
#define Bb 8
#define Cc 512
#define Nn 4096

// Scratch (static __device__ globals: allowed; runtime alloc is not)
__device__ float g_energy[Bb * Cc * Cc];   // 8 MB, reused in-place as attention
__device__ float g_attout[Bb * Cc * Nn];   // 64 MB

// ---------------------------------------------------------------------------
// Kernel 1: energy[b,c,d] = sum_n q[b,c,n] * q[b,d,n]   (Gram matrix per batch)
// Guarded: exits immediately when gamma[0] == 0 (output is then unused).
// ---------------------------------------------------------------------------
__global__ void gram_kernel(const float* __restrict__ x,
                            const float* __restrict__ gamma) {
    if (gamma[0] == 0.0f) return;

    __shared__ float As[32][33];
    __shared__ float Bs[32][33];

    int b  = blockIdx.z;
    int c0 = blockIdx.y * 32;   // row tile (c)
    int d0 = blockIdx.x * 32;   // col tile (d)
    int ty = threadIdx.y, tx = threadIdx.x;

    const float* q = x + (size_t)b * Cc * Nn;
    float acc = 0.0f;

    for (int k0 = 0; k0 < Nn; k0 += 32) {
        As[ty][tx] = q[(size_t)(c0 + ty) * Nn + k0 + tx];
        Bs[ty][tx] = q[(size_t)(d0 + ty) * Nn + k0 + tx];
        __syncthreads();
#pragma unroll
        for (int k = 0; k < 32; k++)
            acc += As[ty][k] * Bs[tx][k];
        __syncthreads();
    }
    g_energy[(size_t)b * Cc * Cc + (size_t)(c0 + ty) * Cc + (d0 + tx)] = acc;
}

// ---------------------------------------------------------------------------
// Kernel 2: softmax over d of (rowmax(energy) - energy), in place.
// One block per (b,c) row of length C=512.
// ---------------------------------------------------------------------------
__global__ void softmax_kernel(const float* __restrict__ gamma) {
    if (gamma[0] == 0.0f) return;

    int row = blockIdx.x;               // 0 .. B*C-1
    float* e = g_energy + (size_t)row * Cc;
    int tid = threadIdx.x;               // 256 threads

    __shared__ float red[256];

    // rowmax and rowmin of energy
    float mx = -3.4e38f, mn = 3.4e38f;
    for (int d = tid; d < Cc; d += 256) {
        float v = e[d];
        mx = fmaxf(mx, v);
        mn = fminf(mn, v);
    }
    red[tid] = mx; __syncthreads();
    for (int s = 128; s > 0; s >>= 1) {
        if (tid < s) red[tid] = fmaxf(red[tid], red[tid + s]);
        __syncthreads();
    }
    float rowmax = red[0]; __syncthreads();

    red[tid] = mn; __syncthreads();
    for (int s = 128; s > 0; s >>= 1) {
        if (tid < s) red[tid] = fminf(red[tid], red[tid + s]);
        __syncthreads();
    }
    float rowmin = red[0]; __syncthreads();

    // v_d = rowmax - e_d ; softmax(v) = exp(v - max(v)) / sum
    // max over d of v = rowmax - rowmin
    float shift = rowmax - rowmin;       // max of v
    float lsum = 0.0f;
    for (int d = tid; d < Cc; d += 256) {
        float v = (rowmax - e[d]) - shift;  // = rowmin - e[d]  (<= 0)
        float ev = __expf(v);
        e[d] = ev;                           // store numerator temporarily
        lsum += ev;
    }
    red[tid] = lsum; __syncthreads();
    for (int s = 128; s > 0; s >>= 1) {
        if (tid < s) red[tid] += red[tid + s];
        __syncthreads();
    }
    float inv = 1.0f / red[0]; __syncthreads();

    for (int d = tid; d < Cc; d += 256)
        e[d] *= inv;
}

// ---------------------------------------------------------------------------
// Kernel 3: attout[b,c,n] = sum_d attn[b,c,d] * q[b,d,n]
// ---------------------------------------------------------------------------
__global__ void av_kernel(const float* __restrict__ x,
                          const float* __restrict__ gamma) {
    if (gamma[0] == 0.0f) return;

    __shared__ float As[32][33];   // attn tile [c][d]
    __shared__ float Bs[32][33];   // q tile    [d][n]

    int b  = blockIdx.z;
    int c0 = blockIdx.y * 32;
    int n0 = blockIdx.x * 32;
    int ty = threadIdx.y, tx = threadIdx.x;

    const float* attn = g_energy + (size_t)b * Cc * Cc;
    const float* q    = x + (size_t)b * Cc * Nn;

    float acc = 0.0f;
    for (int k0 = 0; k0 < Cc; k0 += 32) {
        As[ty][tx] = attn[(size_t)(c0 + ty) * Cc + k0 + tx];
        Bs[ty][tx] = q[(size_t)(k0 + ty) * Nn + n0 + tx];
        __syncthreads();
#pragma unroll
        for (int k = 0; k < 32; k++)
            acc += As[ty][k] * Bs[k][tx];
        __syncthreads();
    }
    g_attout[(size_t)b * Cc * Nn + (size_t)(c0 + ty) * Nn + (n0 + tx)] = acc;
}

// ---------------------------------------------------------------------------
// Kernel 4: result = (gamma==0) ? x : x + gamma * attout.  Vectorized float4.
// ---------------------------------------------------------------------------
__global__ void epilogue_kernel(const float* __restrict__ x,
                                const float* __restrict__ gamma,
                                float* __restrict__ out,
                                int n4) {
    int i = blockIdx.x * blockDim.x + threadIdx.x;
    if (i >= n4) return;
    float g = gamma[0];
    float4 xv = reinterpret_cast<const float4*>(x)[i];
    if (g != 0.0f) {
        float4 av = reinterpret_cast<const float4*>(g_attout)[i];
        xv.x = fmaf(g, av.x, xv.x);
        xv.y = fmaf(g, av.y, xv.y);
        xv.z = fmaf(g, av.z, xv.z);
        xv.w = fmaf(g, av.w, xv.w);
    }
    reinterpret_cast<float4*>(out)[i] = xv;
}

// ---------------------------------------------------------------------------
extern "C" void kernel_launch(void* const* d_in, const int* in_sizes, int n_in,
                              void* d_out, int out_size) {
    const float* x     = (const float*)d_in[0];
    // d_in[1] = y (dead code in the reference)
    const float* gamma = (const float*)d_in[2];
    float* out = (float*)d_out;

    // Heavy path (device-side early-exit when gamma[0]==0)
    {
        dim3 t(32, 32);
        dim3 g1(Cc / 32, Cc / 32, Bb);           // 16 x 16 x 8
        gram_kernel<<<g1, t>>>(x, gamma);

        softmax_kernel<<<Bb * Cc, 256>>>(gamma);

        dim3 g2(Nn / 32, Cc / 32, Bb);           // 128 x 16 x 8
        av_kernel<<<g2, t>>>(x, gamma);
    }

    // Epilogue: always runs, writes every output element
    int n4 = out_size / 4;                        // 2,097,152
    epilogue_kernel<<<(n4 + 255) / 256, 256>>>(x, gamma, out, n4);
}

// round 4
// speedup vs baseline: 2.0348x; 2.0348x over previous
#include <cuda_runtime.h>

// Shapes fixed by the problem: B=8, C=512, H=W=64 -> N=4096
#define Bb 8
#define Cc 512
#define Nn 4096

// Scratch (static __device__ global; runtime alloc forbidden)
__device__ float g_energy[Bb * Cc * Cc];   // 8 MB, reused in-place as attention

#define GRAM_TILES   ((Cc / 32) * (Cc / 32) * Bb)   // 2048
#define AV_TILES     ((Nn / 32) * (Cc / 32) * Bb)   // 16384
#define PERSIST_CTAS 296                             // ~2 CTAs/SM on 148 SMs

// ---------------------------------------------------------------------------
// Kernel 1 (persistent): energy[b,c,d] = sum_n q[b,c,n] * q[b,d,n]
// Exits in one wave when gamma[0] == 0.
// ---------------------------------------------------------------------------
__global__ __launch_bounds__(1024, 2)
void gram_kernel(const float* __restrict__ x,
                 const float* __restrict__ gamma) {
    if (gamma[0] == 0.0f) return;

    __shared__ float As[32][33];
    __shared__ float Bs[32][33];
    int ty = threadIdx.y, tx = threadIdx.x;

    for (int tile = blockIdx.x; tile < GRAM_TILES; tile += gridDim.x) {
        int t  = tile;
        int dx = t % (Cc / 32); t /= (Cc / 32);
        int cy = t % (Cc / 32); t /= (Cc / 32);
        int b  = t;
        int c0 = cy * 32, d0 = dx * 32;

        const float* q = x + (size_t)b * Cc * Nn;
        float acc = 0.0f;

        for (int k0 = 0; k0 < Nn; k0 += 32) {
            As[ty][tx] = q[(size_t)(c0 + ty) * Nn + k0 + tx];
            Bs[ty][tx] = q[(size_t)(d0 + ty) * Nn + k0 + tx];
            __syncthreads();
#pragma unroll
            for (int k = 0; k < 32; k++)
                acc += As[ty][k] * Bs[tx][k];
            __syncthreads();
        }
        g_energy[(size_t)b * Cc * Cc + (size_t)(c0 + ty) * Cc + (d0 + tx)] = acc;
        __syncthreads();
    }
}

// ---------------------------------------------------------------------------
// Kernel 2 (persistent): softmax over d of (rowmax(energy) - energy), in place.
// ---------------------------------------------------------------------------
__global__ __launch_bounds__(256)
void softmax_kernel(const float* __restrict__ gamma) {
    if (gamma[0] == 0.0f) return;

    __shared__ float red[256];
    int tid = threadIdx.x;

    for (int row = blockIdx.x; row < Bb * Cc; row += gridDim.x) {
        float* e = g_energy + (size_t)row * Cc;

        float mx = -3.4e38f, mn = 3.4e38f;
        for (int d = tid; d < Cc; d += 256) {
            float v = e[d];
            mx = fmaxf(mx, v);
            mn = fminf(mn, v);
        }
        red[tid] = mx; __syncthreads();
        for (int s = 128; s > 0; s >>= 1) {
            if (tid < s) red[tid] = fmaxf(red[tid], red[tid + s]);
            __syncthreads();
        }
        float rowmax = red[0]; __syncthreads();

        red[tid] = mn; __syncthreads();
        for (int s = 128; s > 0; s >>= 1) {
            if (tid < s) red[tid] = fminf(red[tid], red[tid + s]);
            __syncthreads();
        }
        float rowmin = red[0]; __syncthreads();

        // v_d = rowmax - e_d ; softmax(v) = exp(v - (rowmax-rowmin)) / sum
        float lsum = 0.0f;
        for (int d = tid; d < Cc; d += 256) {
            float ev = __expf(rowmin - e[d]);   // (rowmax-e) - (rowmax-rowmin)
            e[d] = ev;
            lsum += ev;
        }
        red[tid] = lsum; __syncthreads();
        for (int s = 128; s > 0; s >>= 1) {
            if (tid < s) red[tid] += red[tid + s];
            __syncthreads();
        }
        float inv = 1.0f / red[0]; __syncthreads();

        for (int d = tid; d < Cc; d += 256)
            e[d] *= inv;
        __syncthreads();
    }
}

// ---------------------------------------------------------------------------
// Kernel 3 (persistent): out[b,c,n] = x[b,c,n] + gamma * sum_d attn[b,c,d]*q[b,d,n]
// (out already holds x from the memcpy; we overwrite with x + gamma*attn@q,
//  reading x directly so ordering with the memcpy is irrelevant per-element.)
// ---------------------------------------------------------------------------
__global__ __launch_bounds__(1024, 2)
void av_kernel(const float* __restrict__ x,
               const float* __restrict__ gamma,
               float* __restrict__ out) {
    float g = gamma[0];
    if (g == 0.0f) return;

    __shared__ float As[32][33];   // attn tile [c][d]
    __shared__ float Bs[32][33];   // q tile    [d][n]
    int ty = threadIdx.y, tx = threadIdx.x;

    for (int tile = blockIdx.x; tile < AV_TILES; tile += gridDim.x) {
        int t  = tile;
        int nx = t % (Nn / 32); t /= (Nn / 32);
        int cy = t % (Cc / 32); t /= (Cc / 32);
        int b  = t;
        int c0 = cy * 32, n0 = nx * 32;

        const float* attn = g_energy + (size_t)b * Cc * Cc;
        const float* q    = x + (size_t)b * Cc * Nn;

        float acc = 0.0f;
        for (int k0 = 0; k0 < Cc; k0 += 32) {
            As[ty][tx] = attn[(size_t)(c0 + ty) * Cc + k0 + tx];
            Bs[ty][tx] = q[(size_t)(k0 + ty) * Nn + n0 + tx];
            __syncthreads();
#pragma unroll
            for (int k = 0; k < 32; k++)
                acc += As[ty][k] * Bs[k][tx];
            __syncthreads();
        }
        size_t idx = (size_t)b * Cc * Nn + (size_t)(c0 + ty) * Nn + (n0 + tx);
        out[idx] = fmaf(g, acc, x[idx]);
        __syncthreads();
    }
}

// ---------------------------------------------------------------------------
extern "C" void kernel_launch(void* const* d_in, const int* in_sizes, int n_in,
                              void* d_out, int out_size) {
    const float* x     = (const float*)d_in[0];
    // d_in[1] = y (dead code in the reference)
    const float* gamma = (const float*)d_in[2];
    float* out = (float*)d_out;

    // 1) out = x  (always; driver D2D copy runs near memory roofline)
    cudaMemcpyAsync(out, x, (size_t)out_size * sizeof(float),
                    cudaMemcpyDeviceToDevice);

    // 2) Heavy path: persistent kernels, one-wave early exit when gamma==0.
    dim3 t(32, 32);
    gram_kernel<<<PERSIST_CTAS, t>>>(x, gamma);
    softmax_kernel<<<592, 256>>>(gamma);
    av_kernel<<<PERSIST_CTAS, t>>>(x, gamma, out);
}

// round 7
// speedup vs baseline: 2.4664x; 1.2121x over previous
#include <cuda_runtime.h>

// Shapes fixed by the problem: B=8, C=512, H=W=64 -> N=4096
#define Bb 8
#define Cc 512
#define Nn 4096
#define TOTAL_ELEMS (Bb * Cc * Nn)          // 16,777,216 floats
#define TOTAL_F4    (TOTAL_ELEMS / 4)       // 4,194,304 float4

#define GRAM_TILES   ((Cc / 32) * (Cc / 32) * Bb)   // 2048
#define AV_TILES     ((Nn / 32) * (Cc / 32) * Bb)   // 16384
#define PERSIST_CTAS 296                             // exactly 2 CTAs/SM * 148 SMs

// Scratch + barrier state (static __device__ globals; runtime alloc forbidden)
__device__ float g_energy[Bb * Cc * Cc];            // 8 MB, reused in-place
__device__ unsigned int g_bar_count = 0;
__device__ volatile unsigned int g_bar_sense = 0;

// Software grid barrier. Safe because all PERSIST_CTAS CTAs are co-resident
// (grid == 2 * numSMs at occupancy 2). Sense increments monotonically; each
// launch that uses it flips it exactly twice, and the local sense is re-read
// fresh at each barrier, so graph replays are deterministic.
__device__ __forceinline__ void grid_barrier() {
    __syncthreads();
    if (threadIdx.x == 0 && threadIdx.y == 0) {
        unsigned int s = g_bar_sense;          // read BEFORE arriving (safe: flip
                                               // cannot happen until we arrive)
        __threadfence();                       // publish our writes
        unsigned int arr = atomicAdd(&g_bar_count, 1u);
        if (arr == PERSIST_CTAS - 1) {
            g_bar_count = 0;
            __threadfence();
            g_bar_sense = s + 1;               // release
        } else {
            while (g_bar_sense == s) { }       // volatile spin
            __threadfence();                   // acquire
        }
    }
    __syncthreads();
}

// ---------------------------------------------------------------------------
// Single fused kernel.
//   gamma[0] == 0 : out = x  (pure float4 copy, HBM-bound)
//   gamma[0] != 0 : energy = q q^T -> softmax(rowmax - energy) -> out = x + g*(attn @ q)
// ---------------------------------------------------------------------------
__global__ __launch_bounds__(1024, 2)
void cam_fused_kernel(const float* __restrict__ x,
                      const float* __restrict__ gamma,
                      float* __restrict__ out) {
    float g = __ldg(gamma);

    if (g == 0.0f) {
        // ---- Fast path: out = x. Grid-stride float4 copy, unrolled x4 for MLP.
        int tid    = threadIdx.y * 32 + threadIdx.x;
        int stride = gridDim.x * 1024;
        int i      = blockIdx.x * 1024 + tid;
        const float4* __restrict__ src = reinterpret_cast<const float4*>(x);
        float4* __restrict__ dst       = reinterpret_cast<float4*>(out);

        // TOTAL_F4 = 4,194,304 ; stride = 303,104 -> 13 full strides + remainder
        #pragma unroll 4
        for (; i + 3 * stride < TOTAL_F4; i += 4 * stride) {
            float4 a = src[i];
            float4 b = src[i + stride];
            float4 c = src[i + 2 * stride];
            float4 d = src[i + 3 * stride];
            dst[i]              = a;
            dst[i + stride]     = b;
            dst[i + 2 * stride] = c;
            dst[i + 3 * stride] = d;
        }
        for (; i < TOTAL_F4; i += stride)
            dst[i] = src[i];
        return;
    }

    // ---- Heavy path (correct for any gamma != 0) ----
    __shared__ float As[32][33];
    __shared__ float Bs[32][33];
    int ty = threadIdx.y, tx = threadIdx.x;

    // Phase 1: energy[b,c,d] = sum_n q[b,c,n] * q[b,d,n]
    for (int tile = blockIdx.x; tile < GRAM_TILES; tile += gridDim.x) {
        int t  = tile;
        int dx = t % (Cc / 32); t /= (Cc / 32);
        int cy = t % (Cc / 32); t /= (Cc / 32);
        int b  = t;
        int c0 = cy * 32, d0 = dx * 32;

        const float* q = x + (size_t)b * Cc * Nn;
        float acc = 0.0f;
        for (int k0 = 0; k0 < Nn; k0 += 32) {
            As[ty][tx] = q[(size_t)(c0 + ty) * Nn + k0 + tx];
            Bs[ty][tx] = q[(size_t)(d0 + ty) * Nn + k0 + tx];
            __syncthreads();
#pragma unroll
            for (int k = 0; k < 32; k++)
                acc += As[ty][k] * Bs[tx][k];
            __syncthreads();
        }
        g_energy[(size_t)b * Cc * Cc + (size_t)(c0 + ty) * Cc + (d0 + tx)] = acc;
        __syncthreads();
    }

    grid_barrier();

    // Phase 2: softmax over d of (rowmax - energy), in place.
    // 1024 threads/CTA; treat as linear tid. One row per CTA iteration.
    {
        int tid = ty * 32 + tx;
        __shared__ float red[1024];
        for (int row = blockIdx.x; row < Bb * Cc; row += gridDim.x) {
            float* e = g_energy + (size_t)row * Cc;

            float mx = -3.4e38f, mn = 3.4e38f;
            if (tid < Cc) {                       // Cc=512, threads 512..1023 idle
                float v = e[tid];
                mx = v; mn = v;
            }
            red[tid] = mx; __syncthreads();
            for (int s = 512; s > 0; s >>= 1) {
                if (tid < s) red[tid] = fmaxf(red[tid], red[tid + s]);
                __syncthreads();
            }
            float rowmax = red[0]; __syncthreads();

            red[tid] = mn; __syncthreads();
            for (int s = 512; s > 0; s >>= 1) {
                if (tid < s) red[tid] = fminf(red[tid], red[tid + s]);
                __syncthreads();
            }
            float rowmin = red[0]; __syncthreads();
            (void)rowmax;

            float ev = 0.0f;
            if (tid < Cc) {
                ev = __expf(rowmin - e[tid]);    // (rowmax-e) - (rowmax-rowmin)
            }
            red[tid] = ev; __syncthreads();
            for (int s = 512; s > 0; s >>= 1) {
                if (tid < s) red[tid] += red[tid + s];
                __syncthreads();
            }
            float inv = 1.0f / red[0]; __syncthreads();

            if (tid < Cc)
                e[tid] = ev * inv;
            __syncthreads();
        }
    }

    grid_barrier();

    // Phase 3: out[b,c,n] = x[b,c,n] + g * sum_d attn[b,c,d] * q[b,d,n]
    for (int tile = blockIdx.x; tile < AV_TILES; tile += gridDim.x) {
        int t  = tile;
        int nx = t % (Nn / 32); t /= (Nn / 32);
        int cy = t % (Cc / 32); t /= (Cc / 32);
        int b  = t;
        int c0 = cy * 32, n0 = nx * 32;

        const float* attn = g_energy + (size_t)b * Cc * Cc;
        const float* q    = x + (size_t)b * Cc * Nn;

        float acc = 0.0f;
        for (int k0 = 0; k0 < Cc; k0 += 32) {
            As[ty][tx] = attn[(size_t)(c0 + ty) * Cc + k0 + tx];
            Bs[ty][tx] = q[(size_t)(k0 + ty) * Nn + n0 + tx];
            __syncthreads();
#pragma unroll
            for (int k = 0; k < 32; k++)
                acc += As[ty][k] * Bs[k][tx];
            __syncthreads();
        }
        size_t idx = (size_t)b * Cc * Nn + (size_t)(c0 + ty) * Nn + (n0 + tx);
        out[idx] = fmaf(g, acc, x[idx]);
        __syncthreads();
    }
}

// ---------------------------------------------------------------------------
extern "C" void kernel_launch(void* const* d_in, const int* in_sizes, int n_in,
                              void* d_out, int out_size) {
    const float* x     = (const float*)d_in[0];
    // d_in[1] = y (dead code in the reference)
    const float* gamma = (const float*)d_in[2];
    float* out = (float*)d_out;

    dim3 t(32, 32);
    cam_fused_kernel<<<PERSIST_CTAS, t>>>(x, gamma, out);
}

// round 9
// speedup vs baseline: 2.5750x; 1.0440x over previous
#include <cuda_runtime.h>

// Shapes fixed by the problem: B=8, C=512, H=W=64 -> N=4096
#define Bb 8
#define Cc 512
#define Nn 4096
#define TOTAL_ELEMS (Bb * Cc * Nn)          // 16,777,216 floats
#define TOTAL_F4    (TOTAL_ELEMS / 4)       // 4,194,304 float4

#define GRAM_TILES   ((Cc / 32) * (Cc / 32) * Bb)   // 2048
#define AV_TILES     ((Nn / 32) * (Cc / 32) * Bb)   // 16384
#define NCTA         256                             // <= 296 resident -> barrier safe
#define NTHREADS     (NCTA * 1024)                   // 262,144
#define F4_PER_THR   (TOTAL_F4 / NTHREADS)           // exactly 16

// Scratch + barrier state (static __device__ globals; runtime alloc forbidden)
__device__ float g_energy[Bb * Cc * Cc];            // 8 MB, reused in-place
__device__ unsigned int g_bar_count = 0;
__device__ volatile unsigned int g_bar_sense = 0;

// Software grid barrier. Safe: NCTA=256 <= 296 co-resident CTAs
// (occupancy 2/SM * 148 SMs), all scheduled in wave 1.
__device__ __forceinline__ void grid_barrier() {
    __syncthreads();
    if (threadIdx.x == 0 && threadIdx.y == 0) {
        unsigned int s = g_bar_sense;
        __threadfence();
        unsigned int arr = atomicAdd(&g_bar_count, 1u);
        if (arr == NCTA - 1) {
            g_bar_count = 0;
            __threadfence();
            g_bar_sense = s + 1;
        } else {
            while (g_bar_sense == s) { }
            __threadfence();
        }
    }
    __syncthreads();
}

// ---------------------------------------------------------------------------
// Single fused kernel.
//   gamma[0] == 0 : out = x  (uniform float4 copy: 16/thread, no remainder)
//   gamma[0] != 0 : energy = q q^T -> softmax(rowmax - energy) -> out = x + g*(attn @ q)
// ---------------------------------------------------------------------------
__global__ __launch_bounds__(1024, 2)
void cam_fused_kernel(const float* __restrict__ x,
                      const float* __restrict__ gamma,
                      float* __restrict__ out) {
    float g = __ldg(gamma);

    if (g == 0.0f) {
        // ---- Fast path: out = x. Exactly 16 float4 per thread, stride NTHREADS.
        int tid  = threadIdx.y * 32 + threadIdx.x;
        int base = blockIdx.x * 1024 + tid;
        const float4* __restrict__ src = reinterpret_cast<const float4*>(x);
        float4* __restrict__ dst       = reinterpret_cast<float4*>(out);

        #pragma unroll
        for (int h = 0; h < 2; h++) {
            float4 v[8];
            int b0 = base + h * 8 * NTHREADS;
            #pragma unroll
            for (int j = 0; j < 8; j++)         // 8 independent LDG.128 (MLP=8)
                v[j] = src[b0 + j * NTHREADS];
            #pragma unroll
            for (int j = 0; j < 8; j++)
                dst[b0 + j * NTHREADS] = v[j];
        }
        return;
    }

    // ---- Heavy path (correct for any gamma != 0) ----
    __shared__ float As[32][33];
    __shared__ float Bs[32][33];
    int ty = threadIdx.y, tx = threadIdx.x;

    // Phase 1: energy[b,c,d] = sum_n q[b,c,n] * q[b,d,n]
    for (int tile = blockIdx.x; tile < GRAM_TILES; tile += gridDim.x) {
        int t  = tile;
        int dx = t % (Cc / 32); t /= (Cc / 32);
        int cy = t % (Cc / 32); t /= (Cc / 32);
        int b  = t;
        int c0 = cy * 32, d0 = dx * 32;

        const float* q = x + (size_t)b * Cc * Nn;
        float acc = 0.0f;
        for (int k0 = 0; k0 < Nn; k0 += 32) {
            As[ty][tx] = q[(size_t)(c0 + ty) * Nn + k0 + tx];
            Bs[ty][tx] = q[(size_t)(d0 + ty) * Nn + k0 + tx];
            __syncthreads();
#pragma unroll
            for (int k = 0; k < 32; k++)
                acc += As[ty][k] * Bs[tx][k];
            __syncthreads();
        }
        g_energy[(size_t)b * Cc * Cc + (size_t)(c0 + ty) * Cc + (d0 + tx)] = acc;
        __syncthreads();
    }

    grid_barrier();

    // Phase 2: softmax over d of (rowmax - energy), in place. One row/CTA iter.
    {
        int tid = ty * 32 + tx;
        __shared__ float red[1024];
        for (int row = blockIdx.x; row < Bb * Cc; row += gridDim.x) {
            float* e = g_energy + (size_t)row * Cc;

            float mn = 3.4e38f;
            if (tid < Cc) mn = e[tid];
            red[tid] = mn; __syncthreads();
            for (int s = 512; s > 0; s >>= 1) {
                if (tid < s) red[tid] = fminf(red[tid], red[tid + s]);
                __syncthreads();
            }
            float rowmin = red[0]; __syncthreads();

            // softmax of (rowmax - e) == exp(rowmin - e)/sum  (shift-invariant)
            float ev = 0.0f;
            if (tid < Cc) ev = __expf(rowmin - e[tid]);
            red[tid] = ev; __syncthreads();
            for (int s = 512; s > 0; s >>= 1) {
                if (tid < s) red[tid] += red[tid + s];
                __syncthreads();
            }
            float inv = 1.0f / red[0]; __syncthreads();

            if (tid < Cc) e[tid] = ev * inv;
            __syncthreads();
        }
    }

    grid_barrier();

    // Phase 3: out[b,c,n] = x[b,c,n] + g * sum_d attn[b,c,d] * q[b,d,n]
    for (int tile = blockIdx.x; tile < AV_TILES; tile += gridDim.x) {
        int t  = tile;
        int nx = t % (Nn / 32); t /= (Nn / 32);
        int cy = t % (Cc / 32); t /= (Cc / 32);
        int b  = t;
        int c0 = cy * 32, n0 = nx * 32;

        const float* attn = g_energy + (size_t)b * Cc * Cc;
        const float* q    = x + (size_t)b * Cc * Nn;

        float acc = 0.0f;
        for (int k0 = 0; k0 < Cc; k0 += 32) {
            As[ty][tx] = attn[(size_t)(c0 + ty) * Cc + k0 + tx];
            Bs[ty][tx] = q[(size_t)(k0 + ty) * Nn + n0 + tx];
            __syncthreads();
#pragma unroll
            for (int k = 0; k < 32; k++)
                acc += As[ty][k] * Bs[k][tx];
            __syncthreads();
        }
        size_t idx = (size_t)b * Cc * Nn + (size_t)(c0 + ty) * Nn + (n0 + tx);
        out[idx] = fmaf(g, acc, x[idx]);
        __syncthreads();
    }
}

// ---------------------------------------------------------------------------
extern "C" void kernel_launch(void* const* d_in, const int* in_sizes, int n_in,
                              void* d_out, int out_size) {
    const float* x     = (const float*)d_in[0];
    // d_in[1] = y (dead code in the reference)
    const float* gamma = (const float*)d_in[2];
    float* out = (float*)d_out;

    dim3 t(32, 32);
    cam_fused_kernel<<<NCTA, t>>>(x, gamma, out);
}